// round 14
// baseline (speedup 1.0000x reference)
#include <cuda_runtime.h>
#include <cuda_bf16.h>
#include <cstdint>
#include <cstddef>

#define Bb 128
#define Ll 512
#define Ee 512
#define Hh 8
#define HD 64
#define NBLK 2
#define WIN 64
#define MM (Bb * Ll)   // 65536 rows
#define KK 512

// ---------------- scratch (no allocs allowed -> __device__ globals) ----------------
__device__ float g_x  [(size_t)MM * Ee];
__device__ float g_qin[(size_t)MM * Ee];
__device__ float g_q  [(size_t)MM * Ee];
__device__ float g_kv [(size_t)MM * 2 * Ee];
__device__ float g_o  [(size_t)MM * Ee];
__device__ int   g_mask_mode;                 // 0=uint8, 1=int32, 2=float32

// bf16 hi/lo activation buffers
__device__ __nv_bfloat16 g_xh [(size_t)MM * Ee];
__device__ __nv_bfloat16 g_xl [(size_t)MM * Ee];
__device__ __nv_bfloat16 g_ah [(size_t)MM * Ee];
__device__ __nv_bfloat16 g_al [(size_t)MM * Ee];
__device__ __nv_bfloat16 g_oh [(size_t)MM * Ee];
__device__ __nv_bfloat16 g_ol [(size_t)MM * Ee];
__device__ __nv_bfloat16 g_hh [(size_t)MM * Ee];
__device__ __nv_bfloat16 g_hl [(size_t)MM * Ee];

// bf16 hi/lo weights:  w_in(2*1536*512) | w_out(2*512*512) | c1 | c2
#define OFF_WIN  0
#define OFF_WOUT (2 * 1536 * 512)
#define OFF_C1   (OFF_WOUT + 2 * 512 * 512)
#define OFF_C2   (OFF_C1 + 2 * 512 * 512)
#define W_TOTAL  (OFF_C2 + 2 * 512 * 512)
__device__ __nv_bfloat16 g_wh[(size_t)W_TOTAL];
__device__ __nv_bfloat16 g_wl[(size_t)W_TOTAL];

// ======================= helpers =======================
__device__ __forceinline__ uint32_t smem_to_u32(const void* p) {
    uint32_t a;
    asm("{ .reg .u64 t; cvta.to.shared.u64 t, %1; cvt.u32.u64 %0, t; }" : "=r"(a) : "l"(p));
    return a;
}
__device__ __forceinline__ void ldsm_x4(uint32_t* r, uint32_t addr) {
    asm volatile("ldmatrix.sync.aligned.m8n8.x4.shared.b16 {%0,%1,%2,%3}, [%4];"
                 : "=r"(r[0]), "=r"(r[1]), "=r"(r[2]), "=r"(r[3]) : "r"(addr));
}
__device__ __forceinline__ void mma16816(float* d, const uint32_t* a,
                                         uint32_t b0, uint32_t b1) {
    asm volatile("mma.sync.aligned.m16n8k16.row.col.f32.bf16.bf16.f32 "
                 "{%0,%1,%2,%3}, {%4,%5,%6,%7}, {%8,%9}, {%0,%1,%2,%3};"
                 : "+f"(d[0]), "+f"(d[1]), "+f"(d[2]), "+f"(d[3])
                 : "r"(a[0]), "r"(a[1]), "r"(a[2]), "r"(a[3]), "r"(b0), "r"(b1));
}
__device__ __forceinline__ void cp_async16(uint32_t dst, const void* src) {
    asm volatile("cp.async.cg.shared.global [%0], [%1], 16;" :: "r"(dst), "l"(src));
}
#define CP_COMMIT() asm volatile("cp.async.commit_group;" ::: "memory")
#define CP_WAIT0()  asm volatile("cp.async.wait_group 0;" ::: "memory")

// ---------------- mask dtype detection ----------------
__global__ void detect_mask_kernel(const unsigned char* __restrict__ tm) {
    __shared__ int s_off, s_f32;
    if (threadIdx.x == 0) { s_off = 0; s_f32 = 0; }
    __syncthreads();
    int off = 0, f32 = 0;
    for (int i = threadIdx.x; i < MM; i += blockDim.x) {
        unsigned char b = tm[i];
        if ((i & 3) != 0 && b != 0) off = 1;
        if ((i & 3) == 3 && b == 0x3f) f32 = 1;
    }
    if (off) atomicOr(&s_off, 1);
    if (f32) atomicOr(&s_f32, 1);
    __syncthreads();
    if (threadIdx.x == 0) g_mask_mode = s_f32 ? 2 : (s_off ? 0 : 1);
}
__device__ __forceinline__ bool row_masked(const void* tm, int row, int mode) {
    if (mode == 1) return ((const int*)tm)[row] != 0;
    if (mode == 2) return ((const float*)tm)[row] != 0.0f;
    return ((const unsigned char*)tm)[row] != 0;
}

// hi/lo split store of 4 floats
__device__ __forceinline__ void store_hl4(__nv_bfloat16* H, __nv_bfloat16* L,
                                          size_t off, float4 v) {
    __nv_bfloat16 h[4], l[4];
    h[0] = __float2bfloat16(v.x); l[0] = __float2bfloat16(v.x - __bfloat162float(h[0]));
    h[1] = __float2bfloat16(v.y); l[1] = __float2bfloat16(v.y - __bfloat162float(h[1]));
    h[2] = __float2bfloat16(v.z); l[2] = __float2bfloat16(v.z - __bfloat162float(h[2]));
    h[3] = __float2bfloat16(v.w); l[3] = __float2bfloat16(v.w - __bfloat162float(h[3]));
    *(uint2*)&H[off] = *(uint2*)h;
    *(uint2*)&L[off] = *(uint2*)l;
}

// ---------------- weight fp32 -> bf16 hi/lo ----------------
__global__ void convw_kernel(const float* __restrict__ src,
                             __nv_bfloat16* __restrict__ dh,
                             __nv_bfloat16* __restrict__ dl, int n4) {
    int i = blockIdx.x * 256 + threadIdx.x;
    if (i >= n4) return;
    float4 v = ((const float4*)src)[i];
    store_hl4(dh, dl, (size_t)i * 4, v);
}

// ---------------- x = seqs * keep (+ hi/lo) ----------------
__global__ void mask_mul_kernel(const float* __restrict__ seqs,
                                const void* __restrict__ tm,
                                float* __restrict__ x,
                                __nv_bfloat16* __restrict__ xh,
                                __nv_bfloat16* __restrict__ xl) {
    int idx = blockIdx.x * 256 + threadIdx.x;
    int mode = g_mask_mode;
    float4 v = ((const float4*)seqs)[idx];
    int row = idx >> 7;
    if (row_masked(tm, row, mode)) { v.x = 0.f; v.y = 0.f; v.z = 0.f; v.w = 0.f; }
    ((float4*)x)[idx] = v;
    store_hl4(xh, xl, (size_t)idx * 4, v);
}

// ---------------- row LayerNorm (+ optional hi/lo) ----------------
__global__ void ln_kernel(const float* __restrict__ in, float* __restrict__ out,
                          const float* __restrict__ gamma, const float* __restrict__ beta,
                          __nv_bfloat16* __restrict__ outh, __nv_bfloat16* __restrict__ outl) {
    int row = blockIdx.x;
    int t = threadIdx.x;
    const float4* ip = (const float4*)(in + (size_t)row * Ee);
    float4 v = ip[t];
    __shared__ float red[4];

    float s = v.x + v.y + v.z + v.w;
    #pragma unroll
    for (int o = 16; o; o >>= 1) s += __shfl_xor_sync(0xffffffffu, s, o);
    if ((t & 31) == 0) red[t >> 5] = s;
    __syncthreads();
    float mean = (red[0] + red[1] + red[2] + red[3]) * (1.0f / Ee);

    float dx = v.x - mean, dy = v.y - mean, dz = v.z - mean, dw = v.w - mean;
    float ss = dx * dx + dy * dy + dz * dz + dw * dw;
    __syncthreads();
    #pragma unroll
    for (int o = 16; o; o >>= 1) ss += __shfl_xor_sync(0xffffffffu, ss, o);
    if ((t & 31) == 0) red[t >> 5] = ss;
    __syncthreads();
    float var = (red[0] + red[1] + red[2] + red[3]) * (1.0f / Ee);
    float inv = rsqrtf(var + 1e-8f);

    float4 g = ((const float4*)gamma)[t];
    float4 b = ((const float4*)beta)[t];
    float4 o4;
    o4.x = dx * inv * g.x + b.x;
    o4.y = dy * inv * g.y + b.y;
    o4.z = dz * inv * g.z + b.z;
    o4.w = dw * inv * g.w + b.w;
    size_t off = (size_t)row * Ee + t * 4;
    *(float4*)(out + off) = o4;
    if (outh) store_hl4(outh, outl, off, o4);
}

// ---------------- split-bf16 HMMA GEMM, cp.async 2-stage pipeline ----------------
// C[M,N] = (Ah+Al)[M,512] @ ((Wh+Wl)[N,512])^T   (3-term, fp32 accum)
// CTA tile 128x128, BK=32, 256 threads (warps 2m x 4n, warp tile 64x32).
#define ASTR 40                 // bf16 per smem row (32 + 8 pad)
#define BUFE (128 * ASTR)       // elements per buffer (5120)
#define STAGE_B (4 * BUFE * 2)  // bytes per stage (40960)
#define GEMM_SMEM (2 * STAGE_B) // 81920

__global__ void __launch_bounds__(256)
mma_gemm(const __nv_bfloat16* __restrict__ Ah, const __nv_bfloat16* __restrict__ Al,
         const __nv_bfloat16* __restrict__ Wh, const __nv_bfloat16* __restrict__ Wl,
         const float* __restrict__ bias, float* __restrict__ C,
         __nv_bfloat16* __restrict__ Ch, __nv_bfloat16* __restrict__ Cl,
         int N, const float* __restrict__ resid, const void* __restrict__ mask, int relu) {
    extern __shared__ __nv_bfloat16 smdy[];
    uint32_t smem_u = smem_to_u32(smdy);

    int tid = (int)threadIdx.x;
    int lane = tid & 31;
    int wid = tid >> 5;
    int wm = (wid & 1) * 64;
    int wn = (wid >> 1) * 32;
    int bm = blockIdx.y * 128;
    int bn = blockIdx.x * 128;

    const __nv_bfloat16* srcs[4];
    srcs[0] = Ah + (size_t)bm * KK;
    srcs[1] = Al + (size_t)bm * KK;
    srcs[2] = Wh + (size_t)bn * KK;
    srcs[3] = Wl + (size_t)bn * KK;

    // per-thread cp.async mapping: 2048 chunks / 256 thr = 8 each
    int pbuf[8], prow[8], pcol[8];
    #pragma unroll
    for (int i = 0; i < 8; i++) {
        int flat = tid + i * 256;
        pbuf[i] = flat >> 9;
        int rem = flat & 511;
        prow[i] = rem >> 2;
        pcol[i] = rem & 3;
    }

    #define ISSUE_STAGE(KOFS, SB) do { \
        _Pragma("unroll") \
        for (int i = 0; i < 8; i++) { \
            uint32_t dst = smem_u + (SB) + (pbuf[i] * BUFE + prow[i] * ASTR + pcol[i] * 8) * 2; \
            cp_async16(dst, srcs[pbuf[i]] + (size_t)prow[i] * KK + (KOFS) + pcol[i] * 8); \
        } \
        CP_COMMIT(); } while (0)

    // ldmatrix per-lane offsets
    int aRow = (lane & 7) + ((lane >> 3) & 1) * 8;
    int aK   = (lane >> 4) * 8;
    int bRow = (lane & 7) + ((lane >> 4) & 1) * 8;
    int bK   = ((lane >> 3) & 1) * 8;

    float d[4][4][4];
    #pragma unroll
    for (int i = 0; i < 4; i++)
        #pragma unroll
        for (int j = 0; j < 4; j++)
            #pragma unroll
            for (int e = 0; e < 4; e++) d[i][j][e] = 0.f;

    ISSUE_STAGE(0, 0);
    CP_WAIT0();
    __syncthreads();

    #pragma unroll 1
    for (int it = 0; it < 16; it++) {
        uint32_t sb = (it & 1) * STAGE_B;
        if (it < 15) ISSUE_STAGE((it + 1) * 32, (it & 1) ^ 1 ? STAGE_B : 0);

        #pragma unroll
        for (int ks = 0; ks < 2; ks++) {
            int k0s = ks * 16;
            uint32_t aF[4][4], bH[4][2], bL[4][2];
            #pragma unroll
            for (int ntp = 0; ntp < 2; ntp++) {
                uint32_t r[4];
                uint32_t ab = smem_u + sb + 2 * (2 * BUFE + (wn + ntp * 16 + bRow) * ASTR + k0s + bK);
                ldsm_x4(r, ab);
                bH[ntp * 2][0] = r[0]; bH[ntp * 2][1] = r[1];
                bH[ntp * 2 + 1][0] = r[2]; bH[ntp * 2 + 1][1] = r[3];
                ldsm_x4(r, ab + 2 * BUFE);    // Wl = next buffer
                bL[ntp * 2][0] = r[0]; bL[ntp * 2][1] = r[1];
                bL[ntp * 2 + 1][0] = r[2]; bL[ntp * 2 + 1][1] = r[3];
            }
            #pragma unroll
            for (int mt = 0; mt < 4; mt++)
                ldsm_x4(aF[mt], smem_u + sb + 2 * ((wm + mt * 16 + aRow) * ASTR + k0s + aK));
            #pragma unroll
            for (int mt = 0; mt < 4; mt++)
                #pragma unroll
                for (int nt = 0; nt < 4; nt++)
                    mma16816(d[mt][nt], aF[mt], bH[nt][0], bH[nt][1]);
            #pragma unroll
            for (int mt = 0; mt < 4; mt++)
                #pragma unroll
                for (int nt = 0; nt < 4; nt++)
                    mma16816(d[mt][nt], aF[mt], bL[nt][0], bL[nt][1]);
            #pragma unroll
            for (int mt = 0; mt < 4; mt++)
                ldsm_x4(aF[mt], smem_u + sb + 2 * (BUFE + (wm + mt * 16 + aRow) * ASTR + k0s + aK));
            #pragma unroll
            for (int mt = 0; mt < 4; mt++)
                #pragma unroll
                for (int nt = 0; nt < 4; nt++)
                    mma16816(d[mt][nt], aF[mt], bH[nt][0], bH[nt][1]);
        }
        if (it < 15) CP_WAIT0();
        __syncthreads();
    }

    // ---- epilogue
    int g = lane >> 2;
    int t2 = (lane & 3) * 2;
    int mode = mask ? g_mask_mode : 0;

    #pragma unroll
    for (int mt = 0; mt < 4; mt++) {
        int row0 = bm + wm + mt * 16 + g;
        int row1 = row0 + 8;
        bool m0 = mask && row_masked(mask, row0, mode);
        bool m1 = mask && row_masked(mask, row1, mode);
        #pragma unroll
        for (int nt = 0; nt < 4; nt++) {
            int col = bn + wn + nt * 8 + t2;
            float2 b2 = *(const float2*)(bias + col);
            float v0 = d[mt][nt][0] + b2.x;
            float v1 = d[mt][nt][1] + b2.y;
            float v2 = d[mt][nt][2] + b2.x;
            float v3 = d[mt][nt][3] + b2.y;
            size_t off0 = (size_t)row0 * N + col;
            size_t off1 = (size_t)row1 * N + col;
            if (resid) {
                float2 r0 = *(const float2*)(resid + off0);
                float2 r1 = *(const float2*)(resid + off1);
                v0 += r0.x; v1 += r0.y; v2 += r1.x; v3 += r1.y;
            }
            if (relu) {
                v0 = fmaxf(v0, 0.f); v1 = fmaxf(v1, 0.f);
                v2 = fmaxf(v2, 0.f); v3 = fmaxf(v3, 0.f);
            }
            if (m0) { v0 = 0.f; v1 = 0.f; }
            if (m1) { v2 = 0.f; v3 = 0.f; }
            if (C) {
                float2 o0 = {v0, v1}, o1 = {v2, v3};
                *(float2*)(C + off0) = o0;
                *(float2*)(C + off1) = o1;
            }
            if (Ch) {
                __nv_bfloat16 h0 = __float2bfloat16(v0), h1 = __float2bfloat16(v1);
                __nv_bfloat16 h2 = __float2bfloat16(v2), h3 = __float2bfloat16(v3);
                __nv_bfloat16 l0 = __float2bfloat16(v0 - __bfloat162float(h0));
                __nv_bfloat16 l1 = __float2bfloat16(v1 - __bfloat162float(h1));
                __nv_bfloat16 l2 = __float2bfloat16(v2 - __bfloat162float(h2));
                __nv_bfloat16 l3 = __float2bfloat16(v3 - __bfloat162float(h3));
                *(uint32_t*)&Ch[off0] = (uint32_t)__bfloat16_as_ushort(h1) << 16 | __bfloat16_as_ushort(h0);
                *(uint32_t*)&Ch[off1] = (uint32_t)__bfloat16_as_ushort(h3) << 16 | __bfloat16_as_ushort(h2);
                *(uint32_t*)&Cl[off0] = (uint32_t)__bfloat16_as_ushort(l1) << 16 | __bfloat16_as_ushort(l0);
                *(uint32_t*)&Cl[off1] = (uint32_t)__bfloat16_as_ushort(l3) << 16 | __bfloat16_as_ushort(l2);
            }
        }
    }
}

// ---------------- banded sliding-window attention (smem-free, L1-resident) --------
// one thread per query; scores are tiny (LN'd inputs, 0.02-scale weights) so
// softmax without max-subtraction is numerically safe and exactly equivalent.
__global__ void __launch_bounds__(64)
attn_kernel(const float* __restrict__ Q, const float* __restrict__ KV,
            float* __restrict__ O,
            __nv_bfloat16* __restrict__ Oh, __nv_bfloat16* __restrict__ Ol) {
    int t = (int)threadIdx.x;
    int i0 = blockIdx.x * 64;
    int h = blockIdx.y;
    int b = blockIdx.z;
    int qi = i0 + t;

    const float* qp = Q + ((size_t)b * Ll + qi) * Ee + h * HD;
    float q[64];
    #pragma unroll
    for (int d4 = 0; d4 < 16; d4++) {
        float4 v = ((const float4*)qp)[d4];
        q[d4 * 4 + 0] = v.x; q[d4 * 4 + 1] = v.y;
        q[d4 * 4 + 2] = v.z; q[d4 * 4 + 3] = v.w;
    }

    const float* kbase = KV + (size_t)b * Ll * (2 * Ee) + h * HD;
    float ov[64];
    #pragma unroll
    for (int d = 0; d < 64; d++) ov[d] = 0.f;
    float sum = 0.f;

    int jlo = qi - 63; if (jlo < 0) jlo = 0;
    #pragma unroll 1
    for (int j = jlo; j <= qi; j++) {
        const float* kp = kbase + (size_t)j * (2 * Ee);
        float a0 = 0.f, a1 = 0.f, a2 = 0.f, a3 = 0.f;
        #pragma unroll
        for (int d = 0; d < 64; d += 4) {
            float4 k4 = *(const float4*)(kp + d);
            a0 += q[d + 0] * k4.x; a1 += q[d + 1] * k4.y;
            a2 += q[d + 2] * k4.z; a3 += q[d + 3] * k4.w;
        }
        float p = __expf(((a0 + a1) + (a2 + a3)) * 0.125f);
        sum += p;
        const float* vp = kp + Ee;
        #pragma unroll
        for (int d = 0; d < 64; d += 4) {
            float4 v4 = *(const float4*)(vp + d);
            ov[d + 0] += p * v4.x; ov[d + 1] += p * v4.y;
            ov[d + 2] += p * v4.z; ov[d + 3] += p * v4.w;
        }
    }
    float inv = 1.0f / sum;

    size_t obase = ((size_t)b * Ll + qi) * Ee + h * HD;
    #pragma unroll
    for (int d4 = 0; d4 < 16; d4++) {
        float4 o4;
        o4.x = ov[d4 * 4 + 0] * inv; o4.y = ov[d4 * 4 + 1] * inv;
        o4.z = ov[d4 * 4 + 2] * inv; o4.w = ov[d4 * 4 + 3] * inv;
        size_t off = obase + d4 * 4;
        *(float4*)(O + off) = o4;
        store_hl4(Oh, Ol, off, o4);
    }
}

// ---------------- host orchestration ----------------
extern "C" void kernel_launch(void* const* d_in, const int* in_sizes, int n_in,
                              void* d_out, int out_size) {
    const void*  tmask = d_in[0];
    const float* seqs  = (const float*)d_in[1];
    const float* w_in  = (const float*)d_in[2];
    const float* b_in  = (const float*)d_in[3];
    const float* w_out = (const float*)d_in[4];
    const float* b_out = (const float*)d_in[5];
    const float* ln1_g = (const float*)d_in[6];
    const float* ln1_b = (const float*)d_in[7];
    const float* ln2_g = (const float*)d_in[8];
    const float* ln2_b = (const float*)d_in[9];
    const float* c1_w  = (const float*)d_in[10];
    const float* c1_b  = (const float*)d_in[11];
    const float* c2_w  = (const float*)d_in[12];
    const float* c2_b  = (const float*)d_in[13];
    const float* lnf_g = (const float*)d_in[14];
    const float* lnf_b = (const float*)d_in[15];
    float* outp = (float*)d_out;

    float *x, *qin, *q, *kv, *o;
    cudaGetSymbolAddress((void**)&x,   g_x);
    cudaGetSymbolAddress((void**)&qin, g_qin);
    cudaGetSymbolAddress((void**)&q,   g_q);
    cudaGetSymbolAddress((void**)&kv,  g_kv);
    cudaGetSymbolAddress((void**)&o,   g_o);
    __nv_bfloat16 *xh, *xl, *ah, *al, *oh, *ol, *hh, *hl, *wh, *wl;
    cudaGetSymbolAddress((void**)&xh, g_xh);
    cudaGetSymbolAddress((void**)&xl, g_xl);
    cudaGetSymbolAddress((void**)&ah, g_ah);
    cudaGetSymbolAddress((void**)&al, g_al);
    cudaGetSymbolAddress((void**)&oh, g_oh);
    cudaGetSymbolAddress((void**)&ol, g_ol);
    cudaGetSymbolAddress((void**)&hh, g_hh);
    cudaGetSymbolAddress((void**)&hl, g_hl);
    cudaGetSymbolAddress((void**)&wh, g_wh);
    cudaGetSymbolAddress((void**)&wl, g_wl);

    cudaFuncSetAttribute(mma_gemm, cudaFuncAttributeMaxDynamicSharedMemorySize, GEMM_SMEM);

    // weights -> bf16 hi/lo
    convw_kernel<<<(2 * 1536 * 512 / 4 + 255) / 256, 256>>>(w_in,  wh + OFF_WIN,  wl + OFF_WIN,  2 * 1536 * 512 / 4);
    convw_kernel<<<(2 * 512 * 512 / 4 + 255) / 256, 256>>>(w_out, wh + OFF_WOUT, wl + OFF_WOUT, 2 * 512 * 512 / 4);
    convw_kernel<<<(2 * 512 * 512 / 4 + 255) / 256, 256>>>(c1_w,  wh + OFF_C1,   wl + OFF_C1,   2 * 512 * 512 / 4);
    convw_kernel<<<(2 * 512 * 512 / 4 + 255) / 256, 256>>>(c2_w,  wh + OFF_C2,   wl + OFF_C2,   2 * 512 * 512 / 4);

    detect_mask_kernel<<<1, 1024>>>((const unsigned char*)tmask);
    mask_mul_kernel<<<(MM * Ee / 4) / 256, 256>>>(seqs, tmask, x, xh, xl);

    for (int blk = 0; blk < NBLK; blk++) {
        const __nv_bfloat16* Wq_h  = wh + OFF_WIN + (size_t)blk * 1536 * 512;
        const __nv_bfloat16* Wq_l  = wl + OFF_WIN + (size_t)blk * 1536 * 512;
        const __nv_bfloat16* Wkv_h = Wq_h + (size_t)512 * 512;
        const __nv_bfloat16* Wkv_l = Wq_l + (size_t)512 * 512;
        const float* bq = b_in + (size_t)blk * 3 * Ee;

        // q_in = LN1(x)  (fp32 + hi/lo)
        ln_kernel<<<MM, 128>>>(x, qin, ln1_g + blk * Ee, ln1_b + blk * Ee, ah, al);
        // q = q_in @ Wq^T + bq
        mma_gemm<<<dim3(4, 512), 256, GEMM_SMEM>>>(ah, al, Wq_h, Wq_l, bq,
                                                   q, nullptr, nullptr, Ee,
                                                   nullptr, nullptr, 0);
        // [k|v] = x @ Wkv^T + bkv
        mma_gemm<<<dim3(8, 512), 256, GEMM_SMEM>>>(xh, xl, Wkv_h, Wkv_l, bq + Ee,
                                                   kv, nullptr, nullptr, 2 * Ee,
                                                   nullptr, nullptr, 0);
        // banded attention (emits o fp32 + hi/lo)
        attn_kernel<<<dim3(Ll / 64, Hh, Bb), 64>>>(q, kv, o, oh, ol);
        // x = q_in + o @ Wout^T + bout
        mma_gemm<<<dim3(4, 512), 256, GEMM_SMEM>>>(oh, ol,
                                                   wh + OFF_WOUT + (size_t)blk * 512 * 512,
                                                   wl + OFF_WOUT + (size_t)blk * 512 * 512,
                                                   b_out + blk * Ee, x, nullptr, nullptr, Ee,
                                                   qin, nullptr, 0);
        // x = LN2(x) in place (fp32 + hi/lo into ah/al)
        ln_kernel<<<MM, 128>>>(x, x, ln2_g + blk * Ee, ln2_b + blk * Ee, ah, al);
        // h = relu(x @ c1^T + b1)  -> hi/lo only
        mma_gemm<<<dim3(4, 512), 256, GEMM_SMEM>>>(ah, al,
                                                   wh + OFF_C1 + (size_t)blk * 512 * 512,
                                                   wl + OFF_C1 + (size_t)blk * 512 * 512,
                                                   c1_b + blk * Ee, nullptr, hh, hl, Ee,
                                                   nullptr, nullptr, 1);
        // x = (h @ c2^T + b2 + x) * keep  (fp32 + hi/lo for next block)
        mma_gemm<<<dim3(4, 512), 256, GEMM_SMEM>>>(hh, hl,
                                                   wh + OFF_C2 + (size_t)blk * 512 * 512,
                                                   wl + OFF_C2 + (size_t)blk * 512 * 512,
                                                   c2_b + blk * Ee, x, xh, xl, Ee,
                                                   x, tmask, 0);
    }

    // out = LNf(x)
    ln_kernel<<<MM, 128>>>(x, outp, lnf_g, lnf_b, nullptr, nullptr);
}

// round 15
// speedup vs baseline: 1.9424x; 1.9424x over previous
#include <cuda_runtime.h>
#include <cuda_bf16.h>
#include <cstdint>
#include <cstddef>

#define Bb 128
#define Ll 512
#define Ee 512
#define Hh 8
#define HD 64
#define NBLK 2
#define WIN 64
#define MM (Bb * Ll)   // 65536 rows
#define KK 512

// ---------------- scratch (no allocs allowed -> __device__ globals) ----------------
__device__ float g_x  [(size_t)MM * Ee];
__device__ float g_qin[(size_t)MM * Ee];
__device__ float g_q  [(size_t)MM * Ee];
__device__ float g_kv [(size_t)MM * 2 * Ee];
__device__ float g_o  [(size_t)MM * Ee];
__device__ int   g_mask_mode;                 // 0=uint8, 1=int32, 2=float32

// bf16 hi/lo activation buffers
__device__ __nv_bfloat16 g_xh [(size_t)MM * Ee];
__device__ __nv_bfloat16 g_xl [(size_t)MM * Ee];
__device__ __nv_bfloat16 g_ah [(size_t)MM * Ee];
__device__ __nv_bfloat16 g_al [(size_t)MM * Ee];
__device__ __nv_bfloat16 g_oh [(size_t)MM * Ee];
__device__ __nv_bfloat16 g_ol [(size_t)MM * Ee];
__device__ __nv_bfloat16 g_hh [(size_t)MM * Ee];
__device__ __nv_bfloat16 g_hl [(size_t)MM * Ee];

// bf16 hi/lo weights:  w_in(2*1536*512) | w_out(2*512*512) | c1 | c2
#define OFF_WIN  0
#define OFF_WOUT (2 * 1536 * 512)
#define OFF_C1   (OFF_WOUT + 2 * 512 * 512)
#define OFF_C2   (OFF_C1 + 2 * 512 * 512)
#define W_TOTAL  (OFF_C2 + 2 * 512 * 512)
__device__ __nv_bfloat16 g_wh[(size_t)W_TOTAL];
__device__ __nv_bfloat16 g_wl[(size_t)W_TOTAL];

// ======================= helpers =======================
__device__ __forceinline__ uint32_t smem_to_u32(const void* p) {
    uint32_t a;
    asm("{ .reg .u64 t; cvta.to.shared.u64 t, %1; cvt.u32.u64 %0, t; }" : "=r"(a) : "l"(p));
    return a;
}
__device__ __forceinline__ void ldsm_x4(uint32_t* r, uint32_t addr) {
    asm volatile("ldmatrix.sync.aligned.m8n8.x4.shared.b16 {%0,%1,%2,%3}, [%4];"
                 : "=r"(r[0]), "=r"(r[1]), "=r"(r[2]), "=r"(r[3]) : "r"(addr));
}
__device__ __forceinline__ void mma16816(float* d, const uint32_t* a,
                                         uint32_t b0, uint32_t b1) {
    asm volatile("mma.sync.aligned.m16n8k16.row.col.f32.bf16.bf16.f32 "
                 "{%0,%1,%2,%3}, {%4,%5,%6,%7}, {%8,%9}, {%0,%1,%2,%3};"
                 : "+f"(d[0]), "+f"(d[1]), "+f"(d[2]), "+f"(d[3])
                 : "r"(a[0]), "r"(a[1]), "r"(a[2]), "r"(a[3]), "r"(b0), "r"(b1));
}
__device__ __forceinline__ void cp_async16(uint32_t dst, const void* src) {
    asm volatile("cp.async.cg.shared.global [%0], [%1], 16;" :: "r"(dst), "l"(src));
}
#define CP_COMMIT() asm volatile("cp.async.commit_group;" ::: "memory")
#define CP_WAIT0()  asm volatile("cp.async.wait_group 0;" ::: "memory")

// ---------------- mask dtype detection ----------------
__global__ void detect_mask_kernel(const unsigned char* __restrict__ tm) {
    __shared__ int s_off, s_f32;
    if (threadIdx.x == 0) { s_off = 0; s_f32 = 0; }
    __syncthreads();
    int off = 0, f32 = 0;
    for (int i = threadIdx.x; i < MM; i += blockDim.x) {
        unsigned char b = tm[i];
        if ((i & 3) != 0 && b != 0) off = 1;
        if ((i & 3) == 3 && b == 0x3f) f32 = 1;
    }
    if (off) atomicOr(&s_off, 1);
    if (f32) atomicOr(&s_f32, 1);
    __syncthreads();
    if (threadIdx.x == 0) g_mask_mode = s_f32 ? 2 : (s_off ? 0 : 1);
}
__device__ __forceinline__ bool row_masked(const void* tm, int row, int mode) {
    if (mode == 1) return ((const int*)tm)[row] != 0;
    if (mode == 2) return ((const float*)tm)[row] != 0.0f;
    return ((const unsigned char*)tm)[row] != 0;
}

// hi/lo split store of 4 floats
__device__ __forceinline__ void store_hl4(__nv_bfloat16* H, __nv_bfloat16* L,
                                          size_t off, float4 v) {
    __nv_bfloat16 h[4], l[4];
    h[0] = __float2bfloat16(v.x); l[0] = __float2bfloat16(v.x - __bfloat162float(h[0]));
    h[1] = __float2bfloat16(v.y); l[1] = __float2bfloat16(v.y - __bfloat162float(h[1]));
    h[2] = __float2bfloat16(v.z); l[2] = __float2bfloat16(v.z - __bfloat162float(h[2]));
    h[3] = __float2bfloat16(v.w); l[3] = __float2bfloat16(v.w - __bfloat162float(h[3]));
    *(uint2*)&H[off] = *(uint2*)h;
    *(uint2*)&L[off] = *(uint2*)l;
}

// ---------------- weight fp32 -> bf16 hi/lo ----------------
__global__ void convw_kernel(const float* __restrict__ src,
                             __nv_bfloat16* __restrict__ dh,
                             __nv_bfloat16* __restrict__ dl, int n4) {
    int i = blockIdx.x * 256 + threadIdx.x;
    if (i >= n4) return;
    float4 v = ((const float4*)src)[i];
    store_hl4(dh, dl, (size_t)i * 4, v);
}

// ---------------- x = seqs * keep (+ hi/lo) ----------------
__global__ void mask_mul_kernel(const float* __restrict__ seqs,
                                const void* __restrict__ tm,
                                float* __restrict__ x,
                                __nv_bfloat16* __restrict__ xh,
                                __nv_bfloat16* __restrict__ xl) {
    int idx = blockIdx.x * 256 + threadIdx.x;
    int mode = g_mask_mode;
    float4 v = ((const float4*)seqs)[idx];
    int row = idx >> 7;
    if (row_masked(tm, row, mode)) { v.x = 0.f; v.y = 0.f; v.z = 0.f; v.w = 0.f; }
    ((float4*)x)[idx] = v;
    store_hl4(xh, xl, (size_t)idx * 4, v);
}

// ---------------- row LayerNorm (+ optional hi/lo) ----------------
__global__ void ln_kernel(const float* __restrict__ in, float* __restrict__ out,
                          const float* __restrict__ gamma, const float* __restrict__ beta,
                          __nv_bfloat16* __restrict__ outh, __nv_bfloat16* __restrict__ outl) {
    int row = blockIdx.x;
    int t = threadIdx.x;
    const float4* ip = (const float4*)(in + (size_t)row * Ee);
    float4 v = ip[t];
    __shared__ float red[4];

    float s = v.x + v.y + v.z + v.w;
    #pragma unroll
    for (int o = 16; o; o >>= 1) s += __shfl_xor_sync(0xffffffffu, s, o);
    if ((t & 31) == 0) red[t >> 5] = s;
    __syncthreads();
    float mean = (red[0] + red[1] + red[2] + red[3]) * (1.0f / Ee);

    float dx = v.x - mean, dy = v.y - mean, dz = v.z - mean, dw = v.w - mean;
    float ss = dx * dx + dy * dy + dz * dz + dw * dw;
    __syncthreads();
    #pragma unroll
    for (int o = 16; o; o >>= 1) ss += __shfl_xor_sync(0xffffffffu, ss, o);
    if ((t & 31) == 0) red[t >> 5] = ss;
    __syncthreads();
    float var = (red[0] + red[1] + red[2] + red[3]) * (1.0f / Ee);
    float inv = rsqrtf(var + 1e-8f);

    float4 g = ((const float4*)gamma)[t];
    float4 b = ((const float4*)beta)[t];
    float4 o4;
    o4.x = dx * inv * g.x + b.x;
    o4.y = dy * inv * g.y + b.y;
    o4.z = dz * inv * g.z + b.z;
    o4.w = dw * inv * g.w + b.w;
    size_t off = (size_t)row * Ee + t * 4;
    *(float4*)(out + off) = o4;
    if (outh) store_hl4(outh, outl, off, o4);
}

// ---------------- split-bf16 HMMA GEMM, cp.async 2-stage pipeline ----------------
// C[M,N] = (Ah+Al)[M,512] @ ((Wh+Wl)[N,512])^T   (3-term, fp32 accum)
// CTA tile 128x128, BK=32, 256 threads (warps 2m x 4n, warp tile 64x32).
#define ASTR 40                 // bf16 per smem row (32 + 8 pad)
#define BUFE (128 * ASTR)       // elements per buffer (5120)
#define STAGE_B (4 * BUFE * 2)  // bytes per stage (40960)
#define GEMM_SMEM (2 * STAGE_B) // 81920

__global__ void __launch_bounds__(256)
mma_gemm(const __nv_bfloat16* __restrict__ Ah, const __nv_bfloat16* __restrict__ Al,
         const __nv_bfloat16* __restrict__ Wh, const __nv_bfloat16* __restrict__ Wl,
         const float* __restrict__ bias, float* __restrict__ C,
         __nv_bfloat16* __restrict__ Ch, __nv_bfloat16* __restrict__ Cl,
         int N, const float* __restrict__ resid, const void* __restrict__ mask, int relu) {
    extern __shared__ __nv_bfloat16 smdy[];
    uint32_t smem_u = smem_to_u32(smdy);

    int tid = (int)threadIdx.x;
    int lane = tid & 31;
    int wid = tid >> 5;
    int wm = (wid & 1) * 64;
    int wn = (wid >> 1) * 32;
    int bm = blockIdx.y * 128;
    int bn = blockIdx.x * 128;

    const __nv_bfloat16* srcs[4];
    srcs[0] = Ah + (size_t)bm * KK;
    srcs[1] = Al + (size_t)bm * KK;
    srcs[2] = Wh + (size_t)bn * KK;
    srcs[3] = Wl + (size_t)bn * KK;

    // per-thread cp.async mapping: 2048 chunks / 256 thr = 8 each
    int pbuf[8], prow[8], pcol[8];
    #pragma unroll
    for (int i = 0; i < 8; i++) {
        int flat = tid + i * 256;
        pbuf[i] = flat >> 9;
        int rem = flat & 511;
        prow[i] = rem >> 2;
        pcol[i] = rem & 3;
    }

    #define ISSUE_STAGE(KOFS, SB) do { \
        _Pragma("unroll") \
        for (int i = 0; i < 8; i++) { \
            uint32_t dst = smem_u + (SB) + (pbuf[i] * BUFE + prow[i] * ASTR + pcol[i] * 8) * 2; \
            cp_async16(dst, srcs[pbuf[i]] + (size_t)prow[i] * KK + (KOFS) + pcol[i] * 8); \
        } \
        CP_COMMIT(); } while (0)

    // ldmatrix per-lane offsets
    int aRow = (lane & 7) + ((lane >> 3) & 1) * 8;
    int aK   = (lane >> 4) * 8;
    int bRow = (lane & 7) + ((lane >> 4) & 1) * 8;
    int bK   = ((lane >> 3) & 1) * 8;

    float d[4][4][4];
    #pragma unroll
    for (int i = 0; i < 4; i++)
        #pragma unroll
        for (int j = 0; j < 4; j++)
            #pragma unroll
            for (int e = 0; e < 4; e++) d[i][j][e] = 0.f;

    ISSUE_STAGE(0, 0);
    CP_WAIT0();
    __syncthreads();

    #pragma unroll 1
    for (int it = 0; it < 16; it++) {
        uint32_t sb = (it & 1) * STAGE_B;
        if (it < 15) ISSUE_STAGE((it + 1) * 32, (it & 1) ^ 1 ? STAGE_B : 0);

        #pragma unroll
        for (int ks = 0; ks < 2; ks++) {
            int k0s = ks * 16;
            uint32_t aF[4][4], bH[4][2], bL[4][2];
            #pragma unroll
            for (int ntp = 0; ntp < 2; ntp++) {
                uint32_t r[4];
                uint32_t ab = smem_u + sb + 2 * (2 * BUFE + (wn + ntp * 16 + bRow) * ASTR + k0s + bK);
                ldsm_x4(r, ab);
                bH[ntp * 2][0] = r[0]; bH[ntp * 2][1] = r[1];
                bH[ntp * 2 + 1][0] = r[2]; bH[ntp * 2 + 1][1] = r[3];
                ldsm_x4(r, ab + 2 * BUFE);    // Wl = next buffer
                bL[ntp * 2][0] = r[0]; bL[ntp * 2][1] = r[1];
                bL[ntp * 2 + 1][0] = r[2]; bL[ntp * 2 + 1][1] = r[3];
            }
            #pragma unroll
            for (int mt = 0; mt < 4; mt++)
                ldsm_x4(aF[mt], smem_u + sb + 2 * ((wm + mt * 16 + aRow) * ASTR + k0s + aK));
            #pragma unroll
            for (int mt = 0; mt < 4; mt++)
                #pragma unroll
                for (int nt = 0; nt < 4; nt++)
                    mma16816(d[mt][nt], aF[mt], bH[nt][0], bH[nt][1]);
            #pragma unroll
            for (int mt = 0; mt < 4; mt++)
                #pragma unroll
                for (int nt = 0; nt < 4; nt++)
                    mma16816(d[mt][nt], aF[mt], bL[nt][0], bL[nt][1]);
            #pragma unroll
            for (int mt = 0; mt < 4; mt++)
                ldsm_x4(aF[mt], smem_u + sb + 2 * (BUFE + (wm + mt * 16 + aRow) * ASTR + k0s + aK));
            #pragma unroll
            for (int mt = 0; mt < 4; mt++)
                #pragma unroll
                for (int nt = 0; nt < 4; nt++)
                    mma16816(d[mt][nt], aF[mt], bH[nt][0], bH[nt][1]);
        }
        if (it < 15) CP_WAIT0();
        __syncthreads();
    }

    // ---- epilogue
    int g = lane >> 2;
    int t2 = (lane & 3) * 2;
    int mode = mask ? g_mask_mode : 0;

    #pragma unroll
    for (int mt = 0; mt < 4; mt++) {
        int row0 = bm + wm + mt * 16 + g;
        int row1 = row0 + 8;
        bool m0 = mask && row_masked(mask, row0, mode);
        bool m1 = mask && row_masked(mask, row1, mode);
        #pragma unroll
        for (int nt = 0; nt < 4; nt++) {
            int col = bn + wn + nt * 8 + t2;
            float2 b2 = *(const float2*)(bias + col);
            float v0 = d[mt][nt][0] + b2.x;
            float v1 = d[mt][nt][1] + b2.y;
            float v2 = d[mt][nt][2] + b2.x;
            float v3 = d[mt][nt][3] + b2.y;
            size_t off0 = (size_t)row0 * N + col;
            size_t off1 = (size_t)row1 * N + col;
            if (resid) {
                float2 r0 = *(const float2*)(resid + off0);
                float2 r1 = *(const float2*)(resid + off1);
                v0 += r0.x; v1 += r0.y; v2 += r1.x; v3 += r1.y;
            }
            if (relu) {
                v0 = fmaxf(v0, 0.f); v1 = fmaxf(v1, 0.f);
                v2 = fmaxf(v2, 0.f); v3 = fmaxf(v3, 0.f);
            }
            if (m0) { v0 = 0.f; v1 = 0.f; }
            if (m1) { v2 = 0.f; v3 = 0.f; }
            if (C) {
                float2 o0 = {v0, v1}, o1 = {v2, v3};
                *(float2*)(C + off0) = o0;
                *(float2*)(C + off1) = o1;
            }
            if (Ch) {
                __nv_bfloat16 h0 = __float2bfloat16(v0), h1 = __float2bfloat16(v1);
                __nv_bfloat16 h2 = __float2bfloat16(v2), h3 = __float2bfloat16(v3);
                __nv_bfloat16 l0 = __float2bfloat16(v0 - __bfloat162float(h0));
                __nv_bfloat16 l1 = __float2bfloat16(v1 - __bfloat162float(h1));
                __nv_bfloat16 l2 = __float2bfloat16(v2 - __bfloat162float(h2));
                __nv_bfloat16 l3 = __float2bfloat16(v3 - __bfloat162float(h3));
                *(uint32_t*)&Ch[off0] = (uint32_t)__bfloat16_as_ushort(h1) << 16 | __bfloat16_as_ushort(h0);
                *(uint32_t*)&Ch[off1] = (uint32_t)__bfloat16_as_ushort(h3) << 16 | __bfloat16_as_ushort(h2);
                *(uint32_t*)&Cl[off0] = (uint32_t)__bfloat16_as_ushort(l1) << 16 | __bfloat16_as_ushort(l0);
                *(uint32_t*)&Cl[off1] = (uint32_t)__bfloat16_as_ushort(l3) << 16 | __bfloat16_as_ushort(l2);
            }
        }
    }
}

// ---------------- kernel 4: banded sliding-window attention (smem, R8 version) ----
// block = 64 threads, one per query; grid = (L/64, H, B)
// smem: Ksh[d][r], Vsh[d][r] transposed (r = 0..127 keys), Qsh[t][d], Ssh[t][jj]
#define KSTR 129
#define QSTR 65
#define ATTN_SMEM ((2 * 64 * KSTR + 2 * 64 * QSTR) * 4)

__global__ void __launch_bounds__(64)
attn_kernel(const float* __restrict__ Q, const float* __restrict__ KV,
            float* __restrict__ O,
            __nv_bfloat16* __restrict__ Oh, __nv_bfloat16* __restrict__ Ol) {
    extern __shared__ float sm[];
    float* Ksh = sm;
    float* Vsh = Ksh + 64 * KSTR;
    float* Qsh = Vsh + 64 * KSTR;
    float* Ssh = Qsh + 64 * QSTR;

    int t = (int)threadIdx.x;
    int grp = t >> 4;
    int ln = t & 15;
    int i0 = blockIdx.x * 64;
    int h = blockIdx.y;
    int b = blockIdx.z;

    size_t kvbase = ((size_t)b * Ll) * (2 * Ee) + h * HD;
    #pragma unroll 4
    for (int rr = 0; rr < 32; rr++) {
        int r = grp + 4 * rr;
        int j = i0 - 64 + r;
        float4 k4 = {0.f, 0.f, 0.f, 0.f}, v4 = {0.f, 0.f, 0.f, 0.f};
        if (j >= 0) {
            const float* p = KV + kvbase + (size_t)j * (2 * Ee) + ln * 4;
            k4 = *(const float4*)p;
            v4 = *(const float4*)(p + Ee);
        }
        int d = ln * 4;
        Ksh[(d + 0) * KSTR + r] = k4.x; Ksh[(d + 1) * KSTR + r] = k4.y;
        Ksh[(d + 2) * KSTR + r] = k4.z; Ksh[(d + 3) * KSTR + r] = k4.w;
        Vsh[(d + 0) * KSTR + r] = v4.x; Vsh[(d + 1) * KSTR + r] = v4.y;
        Vsh[(d + 2) * KSTR + r] = v4.z; Vsh[(d + 3) * KSTR + r] = v4.w;
    }
    size_t qbase = ((size_t)b * Ll + i0) * Ee + h * HD;
    #pragma unroll 4
    for (int qq = 0; qq < 16; qq++) {
        int tq = grp + 4 * qq;
        float4 q4 = *(const float4*)(Q + qbase + (size_t)tq * Ee + ln * 4);
        Qsh[tq * QSTR + ln * 4 + 0] = q4.x;
        Qsh[tq * QSTR + ln * 4 + 1] = q4.y;
        Qsh[tq * QSTR + ln * 4 + 2] = q4.z;
        Qsh[tq * QSTR + ln * 4 + 3] = q4.w;
    }
    __syncthreads();

    float q[64];
    #pragma unroll
    for (int d = 0; d < 64; d++) q[d] = Qsh[t * QSTR + d];

    int qi = i0 + t;
    float mx = -1e30f;
    for (int jj = 0; jj < 64; jj++) {
        int r = t + 1 + jj;
        float a0 = 0.f, a1 = 0.f, a2 = 0.f, a3 = 0.f;
        #pragma unroll
        for (int d = 0; d < 64; d += 4) {
            a0 += q[d + 0] * Ksh[(d + 0) * KSTR + r];
            a1 += q[d + 1] * Ksh[(d + 1) * KSTR + r];
            a2 += q[d + 2] * Ksh[(d + 2) * KSTR + r];
            a3 += q[d + 3] * Ksh[(d + 3) * KSTR + r];
        }
        float s = ((a0 + a1) + (a2 + a3)) * 0.125f;
        if (jj + qi < 63) s = -1e30f;
        Ssh[t * QSTR + jj] = s;
        mx = fmaxf(mx, s);
    }

    float sum = 0.f;
    for (int jj = 0; jj < 64; jj++) {
        float p = __expf(Ssh[t * QSTR + jj] - mx);
        Ssh[t * QSTR + jj] = p;
        sum += p;
    }
    float inv = 1.0f / sum;

    float ov[64];
    #pragma unroll
    for (int d = 0; d < 64; d++) ov[d] = 0.f;
    for (int jj = 0; jj < 64; jj++) {
        float p = Ssh[t * QSTR + jj];
        int r = t + 1 + jj;
        #pragma unroll
        for (int d = 0; d < 64; d++)
            ov[d] += p * Vsh[d * KSTR + r];
    }

    __syncthreads();
    #pragma unroll
    for (int d = 0; d < 64; d++) Qsh[t * QSTR + d] = ov[d] * inv;
    __syncthreads();

    size_t obase = ((size_t)b * Ll + i0) * Ee + h * HD;
    #pragma unroll 4
    for (int qq = 0; qq < 16; qq++) {
        int tq = grp + 4 * qq;
        float4 o4;
        o4.x = Qsh[tq * QSTR + ln * 4 + 0];
        o4.y = Qsh[tq * QSTR + ln * 4 + 1];
        o4.z = Qsh[tq * QSTR + ln * 4 + 2];
        o4.w = Qsh[tq * QSTR + ln * 4 + 3];
        size_t off = obase + (size_t)tq * Ee + ln * 4;
        *(float4*)(O + off) = o4;
        store_hl4(Oh, Ol, off, o4);
    }
}

// ---------------- host orchestration ----------------
extern "C" void kernel_launch(void* const* d_in, const int* in_sizes, int n_in,
                              void* d_out, int out_size) {
    const void*  tmask = d_in[0];
    const float* seqs  = (const float*)d_in[1];
    const float* w_in  = (const float*)d_in[2];
    const float* b_in  = (const float*)d_in[3];
    const float* w_out = (const float*)d_in[4];
    const float* b_out = (const float*)d_in[5];
    const float* ln1_g = (const float*)d_in[6];
    const float* ln1_b = (const float*)d_in[7];
    const float* ln2_g = (const float*)d_in[8];
    const float* ln2_b = (const float*)d_in[9];
    const float* c1_w  = (const float*)d_in[10];
    const float* c1_b  = (const float*)d_in[11];
    const float* c2_w  = (const float*)d_in[12];
    const float* c2_b  = (const float*)d_in[13];
    const float* lnf_g = (const float*)d_in[14];
    const float* lnf_b = (const float*)d_in[15];
    float* outp = (float*)d_out;

    float *x, *qin, *q, *kv, *o;
    cudaGetSymbolAddress((void**)&x,   g_x);
    cudaGetSymbolAddress((void**)&qin, g_qin);
    cudaGetSymbolAddress((void**)&q,   g_q);
    cudaGetSymbolAddress((void**)&kv,  g_kv);
    cudaGetSymbolAddress((void**)&o,   g_o);
    __nv_bfloat16 *xh, *xl, *ah, *al, *oh, *ol, *hh, *hl, *wh, *wl;
    cudaGetSymbolAddress((void**)&xh, g_xh);
    cudaGetSymbolAddress((void**)&xl, g_xl);
    cudaGetSymbolAddress((void**)&ah, g_ah);
    cudaGetSymbolAddress((void**)&al, g_al);
    cudaGetSymbolAddress((void**)&oh, g_oh);
    cudaGetSymbolAddress((void**)&ol, g_ol);
    cudaGetSymbolAddress((void**)&hh, g_hh);
    cudaGetSymbolAddress((void**)&hl, g_hl);
    cudaGetSymbolAddress((void**)&wh, g_wh);
    cudaGetSymbolAddress((void**)&wl, g_wl);

    cudaFuncSetAttribute(mma_gemm, cudaFuncAttributeMaxDynamicSharedMemorySize, GEMM_SMEM);
    cudaFuncSetAttribute(attn_kernel, cudaFuncAttributeMaxDynamicSharedMemorySize, ATTN_SMEM);

    // weights -> bf16 hi/lo
    convw_kernel<<<(2 * 1536 * 512 / 4 + 255) / 256, 256>>>(w_in,  wh + OFF_WIN,  wl + OFF_WIN,  2 * 1536 * 512 / 4);
    convw_kernel<<<(2 * 512 * 512 / 4 + 255) / 256, 256>>>(w_out, wh + OFF_WOUT, wl + OFF_WOUT, 2 * 512 * 512 / 4);
    convw_kernel<<<(2 * 512 * 512 / 4 + 255) / 256, 256>>>(c1_w,  wh + OFF_C1,   wl + OFF_C1,   2 * 512 * 512 / 4);
    convw_kernel<<<(2 * 512 * 512 / 4 + 255) / 256, 256>>>(c2_w,  wh + OFF_C2,   wl + OFF_C2,   2 * 512 * 512 / 4);

    detect_mask_kernel<<<1, 1024>>>((const unsigned char*)tmask);
    mask_mul_kernel<<<(MM * Ee / 4) / 256, 256>>>(seqs, tmask, x, xh, xl);

    for (int blk = 0; blk < NBLK; blk++) {
        const __nv_bfloat16* Wq_h  = wh + OFF_WIN + (size_t)blk * 1536 * 512;
        const __nv_bfloat16* Wq_l  = wl + OFF_WIN + (size_t)blk * 1536 * 512;
        const __nv_bfloat16* Wkv_h = Wq_h + (size_t)512 * 512;
        const __nv_bfloat16* Wkv_l = Wq_l + (size_t)512 * 512;
        const float* bq = b_in + (size_t)blk * 3 * Ee;

        // q_in = LN1(x)  (fp32 + hi/lo)
        ln_kernel<<<MM, 128>>>(x, qin, ln1_g + blk * Ee, ln1_b + blk * Ee, ah, al);
        // q = q_in @ Wq^T + bq
        mma_gemm<<<dim3(4, 512), 256, GEMM_SMEM>>>(ah, al, Wq_h, Wq_l, bq,
                                                   q, nullptr, nullptr, Ee,
                                                   nullptr, nullptr, 0);
        // [k|v] = x @ Wkv^T + bkv
        mma_gemm<<<dim3(8, 512), 256, GEMM_SMEM>>>(xh, xl, Wkv_h, Wkv_l, bq + Ee,
                                                   kv, nullptr, nullptr, 2 * Ee,
                                                   nullptr, nullptr, 0);
        // banded attention (emits o fp32 + hi/lo)
        attn_kernel<<<dim3(Ll / 64, Hh, Bb), 64, ATTN_SMEM>>>(q, kv, o, oh, ol);
        // x = q_in + o @ Wout^T + bout
        mma_gemm<<<dim3(4, 512), 256, GEMM_SMEM>>>(oh, ol,
                                                   wh + OFF_WOUT + (size_t)blk * 512 * 512,
                                                   wl + OFF_WOUT + (size_t)blk * 512 * 512,
                                                   b_out + blk * Ee, x, nullptr, nullptr, Ee,
                                                   qin, nullptr, 0);
        // x = LN2(x) in place (fp32 + hi/lo into ah/al)
        ln_kernel<<<MM, 128>>>(x, x, ln2_g + blk * Ee, ln2_b + blk * Ee, ah, al);
        // h = relu(x @ c1^T + b1)  -> hi/lo only
        mma_gemm<<<dim3(4, 512), 256, GEMM_SMEM>>>(ah, al,
                                                   wh + OFF_C1 + (size_t)blk * 512 * 512,
                                                   wl + OFF_C1 + (size_t)blk * 512 * 512,
                                                   c1_b + blk * Ee, nullptr, hh, hl, Ee,
                                                   nullptr, nullptr, 1);
        // x = (h @ c2^T + b2 + x) * keep  (fp32 + hi/lo for next block)
        mma_gemm<<<dim3(4, 512), 256, GEMM_SMEM>>>(hh, hl,
                                                   wh + OFF_C2 + (size_t)blk * 512 * 512,
                                                   wl + OFF_C2 + (size_t)blk * 512 * 512,
                                                   c2_b + blk * Ee, x, xh, xl, Ee,
                                                   x, tmask, 0);
    }

    // out = LNf(x)
    ln_kernel<<<MM, 128>>>(x, outp, lnf_g, lnf_b, nullptr, nullptr);
}